// round 14
// baseline (speedup 1.0000x reference)
#include <cuda_runtime.h>
#include <cuda_bf16.h>

#define B 32768
#define C 1000
#define NV4 250            // float4 per row
#define NBLK 4096          // 8 rows/block, 1 row/warp, wave-based
#define GATE_TARGET 33u    // 32 hist blocks + 1 out-zeroer

// INVARIANTS at kernel_launch entry (zero at module load, restored by the
// last block each run): g_cnt == 0, g_gate == 0, g_done == 0.
__device__ int      g_cnt[C];
__device__ unsigned g_gate;
__device__ unsigned g_done;

__global__ __launch_bounds__(256) void kl_all_kernel(
    const float* __restrict__ f1,
    const float* __restrict__ f2,
    const int*   __restrict__ label,
    float*       __restrict__ out)
{
    __shared__ float swarp[8];
    __shared__ int   s_last;
    const int tid  = threadIdx.x;
    const int lane = tid & 31;
    const int wid  = tid >> 5;

    // ---- prologue (wave-1 blocks only): hist + out zeroing, then gate ----
    if (blockIdx.x < 32) {
        int i = blockIdx.x * 256 + tid;            // int4 index, 8192 total
        int4 L = ((const int4*)label)[i];
        atomicAdd(&g_cnt[min(max(L.x, 0), C - 1)], 1);
        atomicAdd(&g_cnt[min(max(L.y, 0), C - 1)], 1);
        atomicAdd(&g_cnt[min(max(L.z, 0), C - 1)], 1);
        atomicAdd(&g_cnt[min(max(L.w, 0), C - 1)], 1);
        __syncthreads();                           // all block's atomics issued
        if (tid == 0) {
            __threadfence();
            atomicAdd(&g_gate, 1u);
        }
    }
    if (blockIdx.x == 0 && tid == 0) {
        out[0] = 0.f;                              // d_out is poisoned / accumulates
        __threadfence();
        atomicAdd(&g_gate, 1u);
    }

    // ---- engine: one row per warp, front-batched 16x LDG.128 ----
    const int row = blockIdx.x * 8 + wid;
    int lab = (lane == 0) ? label[row] : 0;        // early, overlaps big loads
    const float4* p1 = (const float4*)f1 + (size_t)row * NV4;
    const float4* p2 = (const float4*)f2 + (size_t)row * NV4;

    float4 a[8], b[8];
    const float4 NEG = make_float4(-1e30f, -1e30f, -1e30f, -1e30f);
    #pragma unroll
    for (int k = 0; k < 8; k++) {
        int j = lane + 32 * k;
        if (j < NV4) { a[k] = p1[j]; b[k] = p2[j]; }
        else         { a[k] = NEG;   b[k] = NEG;   }
    }

    // pass 1: row maxes (consumes whole row -> ptxas front-batches all loads)
    float m1 = -1e30f, m2 = -1e30f;
    #pragma unroll
    for (int k = 0; k < 8; k++) {
        m1 = fmaxf(m1, fmaxf(fmaxf(a[k].x, a[k].y), fmaxf(a[k].z, a[k].w)));
        m2 = fmaxf(m2, fmaxf(fmaxf(b[k].x, b[k].y), fmaxf(b[k].z, b[k].w)));
    }
    #pragma unroll
    for (int o = 16; o; o >>= 1) {
        m1 = fmaxf(m1, __shfl_xor_sync(0xFFFFFFFFu, m1, o));
        m2 = fmaxf(m2, __shfl_xor_sync(0xFFFFFFFFu, m2, o));
    }

    // pass 2 (registers): s1, s2, wv
    float s1 = 0.f, s2 = 0.f, wv = 0.f;
    #pragma unroll
    for (int k = 0; k < 8; k++) {
        s1 += __expf(a[k].x - m1) + __expf(a[k].y - m1)
            + __expf(a[k].z - m1) + __expf(a[k].w - m1);
        float e;
        e = __expf(b[k].x - m2); s2 += e; wv = fmaf(e, b[k].x - a[k].x, wv);
        e = __expf(b[k].y - m2); s2 += e; wv = fmaf(e, b[k].y - a[k].y, wv);
        e = __expf(b[k].z - m2); s2 += e; wv = fmaf(e, b[k].z - a[k].z, wv);
        e = __expf(b[k].w - m2); s2 += e; wv = fmaf(e, b[k].w - a[k].w, wv);
    }
    #pragma unroll
    for (int o = 16; o; o >>= 1) {
        s1 += __shfl_xor_sync(0xFFFFFFFFu, s1, o);
        s2 += __shfl_xor_sync(0xFFFFFFFFu, s2, o);
        wv += __shfl_xor_sync(0xFFFFFFFFu, wv, o);
    }

    // ---- tail (small, straight-line; codegen-safe per R4 evidence) ----
    if (lane == 0) {
        float kl = wv / s2 + (m1 + __logf(s1)) - (m2 + __logf(s2));
        // gate: hist + out-zeroing complete (normally long since satisfied)
        while (atomicAdd(&g_gate, 0u) < GATE_TARGET) { }
        lab = min(max(lab, 0), C - 1);
        float cnt = (float)max(__ldcg(g_cnt + lab), 1);
        swarp[wid] = kl / (cnt * (float)C);
    }
    __syncthreads();
    if (tid == 0) {
        float r = 0.f;
        #pragma unroll
        for (int k = 0; k < 8; k++) r += swarp[k];
        atomicAdd(out, r);
        // completion ticket: last block restores invariants for next replay
        __threadfence();
        unsigned old = atomicAdd(&g_done, 1u);
        s_last = (old == (unsigned)(NBLK - 1)) ? 1 : 0;
    }
    __syncthreads();
    if (s_last) {
        for (int k = tid; k < C; k += 256) g_cnt[k] = 0;
        if (tid == 0) { g_gate = 0u; g_done = 0u; }
    }
}

extern "C" void kernel_launch(void* const* d_in, const int* in_sizes, int n_in,
                              void* d_out, int out_size)
{
    const float* f1    = (const float*)d_in[0];
    const float* f2    = (const float*)d_in[1];
    const int*   label = (const int*)d_in[2];
    float*       out   = (float*)d_out;

    kl_all_kernel<<<NBLK, 256>>>(f1, f2, label, out);
}

// round 15
// speedup vs baseline: 1.5533x; 1.5533x over previous
#include <cuda_runtime.h>
#include <cuda_bf16.h>

#define B 32768
#define C 1000
#define NV4 250            // float4 per row
#define NBLK 4096          // 8 rows/block, 1 row/warp, wave-based
#define NFIN 32            // finisher blocks

// INVARIANTS at kernel_launch entry (zero at module load, restored by kl_final):
//   g_cnt == 0, g_done == 0.
__device__ int      g_cnt[C];
__device__ float    g_row[B];
__device__ float    g_part[NFIN];
__device__ unsigned g_done;

// ---- engine: two-pass row KL + hist prologue; writes RAW kl (no cnt).
// f1/f2 are touched exactly once -> streaming (.cs) loads keep L2 clean. ----
__global__ __launch_bounds__(256) void kl_main_kernel(
    const float* __restrict__ f1,
    const float* __restrict__ f2,
    const int*   __restrict__ label)
{
    const int tid  = threadIdx.x;
    const int lane = tid & 31;
    const int wid  = tid >> 5;

    // hist prologue: blocks 0..31 cover all 32768 labels (int4 loads).
    // g_cnt has no reader until kl_final, so this overlaps with streaming.
    if (blockIdx.x < 32) {
        int i = blockIdx.x * 256 + tid;
        int4 L = ((const int4*)label)[i];
        atomicAdd(&g_cnt[min(max(L.x, 0), C - 1)], 1);
        atomicAdd(&g_cnt[min(max(L.y, 0), C - 1)], 1);
        atomicAdd(&g_cnt[min(max(L.z, 0), C - 1)], 1);
        atomicAdd(&g_cnt[min(max(L.w, 0), C - 1)], 1);
    }

    const int row = blockIdx.x * 8 + wid;
    const float4* p1 = (const float4*)f1 + (size_t)row * NV4;
    const float4* p2 = (const float4*)f2 + (size_t)row * NV4;

    float4 a[8], b[8];
    const float4 NEG = make_float4(-1e30f, -1e30f, -1e30f, -1e30f);
    #pragma unroll
    for (int k = 0; k < 8; k++) {
        int j = lane + 32 * k;
        if (j < NV4) { a[k] = __ldcs(p1 + j); b[k] = __ldcs(p2 + j); }
        else         { a[k] = NEG;            b[k] = NEG;            }
    }

    // pass 1: row maxes (consumes whole row -> ptxas front-batches all loads)
    float m1 = -1e30f, m2 = -1e30f;
    #pragma unroll
    for (int k = 0; k < 8; k++) {
        m1 = fmaxf(m1, fmaxf(fmaxf(a[k].x, a[k].y), fmaxf(a[k].z, a[k].w)));
        m2 = fmaxf(m2, fmaxf(fmaxf(b[k].x, b[k].y), fmaxf(b[k].z, b[k].w)));
    }
    #pragma unroll
    for (int o = 16; o; o >>= 1) {
        m1 = fmaxf(m1, __shfl_xor_sync(0xFFFFFFFFu, m1, o));
        m2 = fmaxf(m2, __shfl_xor_sync(0xFFFFFFFFu, m2, o));
    }

    // pass 2 (registers): s1, s2, wv
    float s1 = 0.f, s2 = 0.f, wv = 0.f;
    #pragma unroll
    for (int k = 0; k < 8; k++) {
        s1 += __expf(a[k].x - m1) + __expf(a[k].y - m1)
            + __expf(a[k].z - m1) + __expf(a[k].w - m1);
        float e;
        e = __expf(b[k].x - m2); s2 += e; wv = fmaf(e, b[k].x - a[k].x, wv);
        e = __expf(b[k].y - m2); s2 += e; wv = fmaf(e, b[k].y - a[k].y, wv);
        e = __expf(b[k].z - m2); s2 += e; wv = fmaf(e, b[k].z - a[k].z, wv);
        e = __expf(b[k].w - m2); s2 += e; wv = fmaf(e, b[k].w - a[k].w, wv);
    }
    #pragma unroll
    for (int o = 16; o; o >>= 1) {
        s1 += __shfl_xor_sync(0xFFFFFFFFu, s1, o);
        s2 += __shfl_xor_sync(0xFFFFFFFFu, s2, o);
        wv += __shfl_xor_sync(0xFFFFFFFFu, wv, o);
    }

    if (lane == 0)
        __stcs(g_row + row, wv / s2 + (m1 + __logf(s1)) - (m2 + __logf(s2)));
}

// ---- finisher: 32 blocks, one int4 of rows per thread; last block (ticket)
// reduces the 32 partials in fixed order and restores invariants. ----
__global__ __launch_bounds__(256) void kl_final_kernel(
    const int* __restrict__ label,
    float*     __restrict__ out)
{
    __shared__ int   scnt[C];
    __shared__ float swarp[8];
    __shared__ int   s_last;
    const int tid  = threadIdx.x;
    const int lane = tid & 31;
    const int wid  = tid >> 5;

    // stage g_cnt in smem (coalesced) so the per-row gather hits smem
    #pragma unroll
    for (int k = 0; k < 4; k++) {
        int c = tid + 256 * k;
        if (c < C) scnt[c] = g_cnt[c];
    }

    const int i = blockIdx.x * 256 + tid;        // int4 index, 8192 total
    float4 v = __ldcg((const float4*)g_row + i);
    int4   L = __ldg((const int4*)label + i);
    L.x = min(max(L.x, 0), C - 1);
    L.y = min(max(L.y, 0), C - 1);
    L.z = min(max(L.z, 0), C - 1);
    L.w = min(max(L.w, 0), C - 1);
    __syncthreads();

    float s = 0.f;
    s += __fdividef(v.x, (float)max(scnt[L.x], 1));
    s += __fdividef(v.y, (float)max(scnt[L.y], 1));
    s += __fdividef(v.z, (float)max(scnt[L.z], 1));
    s += __fdividef(v.w, (float)max(scnt[L.w], 1));

    #pragma unroll
    for (int o = 16; o; o >>= 1) s += __shfl_xor_sync(0xFFFFFFFFu, s, o);
    if (lane == 0) swarp[wid] = s;
    __syncthreads();
    if (tid == 0) {
        float r = 0.f;
        #pragma unroll
        for (int k = 0; k < 8; k++) r += swarp[k];
        g_part[blockIdx.x] = r;
        __threadfence();
        unsigned old = atomicAdd(&g_done, 1u);
        s_last = (old == (unsigned)(NFIN - 1)) ? 1 : 0;
    }
    __syncthreads();
    if (!s_last) return;

    // last block: deterministic fixed-order sum of the 32 partials
    if (wid == 0) {
        float r = (lane < NFIN) ? __ldcg(g_part + lane) : 0.f;
        #pragma unroll
        for (int o = 16; o; o >>= 1) r += __shfl_xor_sync(0xFFFFFFFFu, r, o);
        if (lane == 0) out[0] = r * (1.0f / (float)C);
    }
    // restore invariants for next call / graph replay
    __syncthreads();
    for (int k = tid; k < C; k += 256) g_cnt[k] = 0;
    if (tid == 0) g_done = 0u;
}

extern "C" void kernel_launch(void* const* d_in, const int* in_sizes, int n_in,
                              void* d_out, int out_size)
{
    const float* f1    = (const float*)d_in[0];
    const float* f2    = (const float*)d_in[1];
    const int*   label = (const int*)d_in[2];
    float*       out   = (float*)d_out;

    kl_main_kernel<<<NBLK, 256>>>(f1, f2, label);
    kl_final_kernel<<<NFIN, 256>>>(label, out);
}